// round 1
// baseline (speedup 1.0000x reference)
#include <cuda_runtime.h>
#include <cuda_bf16.h>
#include <math.h>

#define N1 10000
#define N2 10000
#define F_IN 256
#define E_EDGES 480000
#define P_PAIRS 200000
#define HID 128
#define NHEAD 8
#define DH 16

// ---------------- scratch (device globals; no dynamic alloc allowed) ----------------
__device__ float g_h1[N1 * HID];
__device__ float g_h2[N2 * HID];
__device__ float g_q1[N1 * HID];
__device__ float g_k1[N1 * HID];
__device__ float g_v1[N1 * HID];
__device__ float g_q2[N2 * HID];
__device__ float g_k2[N2 * HID];
__device__ float g_v2[N2 * HID];
__device__ float g_f1[2 * N1 * HID];   // per-layer outputs (become h for next layer)
__device__ float g_f2[2 * N2 * HID];
__device__ float g_agg1[N1 * HID];
__device__ float g_agg2[N2 * HID];
__device__ float g_logits[E_EDGES * NHEAD];
__device__ float g_m1[N1 * NHEAD];
__device__ float g_s1[N1 * NHEAD];
__device__ float g_m2[N2 * NHEAD];
__device__ float g_s2[N2 * NHEAD];
__device__ float g_Wf[4][HID * HID];   // folded K1,K2,V1,V2 weights for current layer
__device__ float g_bf[4][HID];

// ---------------- helpers ----------------
__device__ __forceinline__ float gelu_tanh(float x) {
    // jax.nn.gelu(approximate=True)
    const float c = 0.7978845608028654f;
    float t = tanhf(c * (x + 0.044715f * x * x * x));
    return 0.5f * x * (1.0f + t);
}

// ---------------- fold arel/mrel into projection weights ----------------
// Wf[f, h*16+e] = sum_d W[f, h*16+d] * rel[h, d, e]; bf likewise from b.
__global__ void fold_kernel(const float* __restrict__ W, const float* __restrict__ b,
                            const float* __restrict__ rel,
                            float* __restrict__ Wf, float* __restrict__ bf) {
    int t = blockIdx.x * blockDim.x + threadIdx.x;
    if (t >= HID * HID) return;
    int row = t >> 7;
    int col = t & 127;
    int h = col >> 4;
    int eo = col & 15;
    const float* relh = rel + h * (DH * DH);
    const float* wrow = W + row * HID + h * DH;
    float acc = 0.f;
#pragma unroll
    for (int d = 0; d < DH; d++) acc = fmaf(wrow[d], relh[d * DH + eo], acc);
    Wf[t] = acc;
    if (row == 0) {
        const float* brow = b + h * DH;
        float accb = 0.f;
#pragma unroll
        for (int d = 0; d < DH; d++) accb = fmaf(brow[d], relh[d * DH + eo], accb);
        bf[col] = accb;
    }
}

// ---------------- GEMM: C[M,128] = epi( actA(A[M,K]) @ B[K,128] + bias ) ----------------
// epi: 0 = none, 1 = relu, 2 = skip: C = sg*(..) + (1-sg)*Hprev, sg = sigmoid(*skipp)
__global__ void __launch_bounds__(256, 2) gemm_kernel(
    const float* __restrict__ A, const float* __restrict__ B,
    const float* __restrict__ bias, const float* __restrict__ Hprev,
    const float* __restrict__ skipp, float* __restrict__ C,
    int M, int K, int geluA, int epi) {
    __shared__ float As[16][68];   // [k][m], padded
    __shared__ float Bs[16][128];  // [k][n]

    const int tid = threadIdx.x;
    const int m0 = blockIdx.x * 64;
    const int tr = tid >> 4;           // 0..15  -> rows tr*4 .. +3
    const int tc = tid & 15;           // 0..15  -> cols tc*8 .. +7
    const int arow = tid >> 2;         // 0..63
    const int akol = (tid & 3) << 2;   // 0,4,8,12
    const int brow = tid >> 5;         // 0..7
    const int bcol = (tid & 31) << 2;  // 0..124

    float acc[4][8];
#pragma unroll
    for (int i = 0; i < 4; i++)
#pragma unroll
        for (int j = 0; j < 8; j++) acc[i][j] = 0.f;

    const int gr = m0 + arow;
    const float* Aptr = A + (size_t)gr * K;

    for (int k0 = 0; k0 < K; k0 += 16) {
        float4 a4 = make_float4(0.f, 0.f, 0.f, 0.f);
        if (gr < M) a4 = *(const float4*)(Aptr + k0 + akol);
        if (geluA) {
            a4.x = gelu_tanh(a4.x); a4.y = gelu_tanh(a4.y);
            a4.z = gelu_tanh(a4.z); a4.w = gelu_tanh(a4.w);
        }
        As[akol + 0][arow] = a4.x;
        As[akol + 1][arow] = a4.y;
        As[akol + 2][arow] = a4.z;
        As[akol + 3][arow] = a4.w;
        *(float4*)&Bs[brow][bcol]     = *(const float4*)(B + (size_t)(k0 + brow) * HID + bcol);
        *(float4*)&Bs[brow + 8][bcol] = *(const float4*)(B + (size_t)(k0 + brow + 8) * HID + bcol);
        __syncthreads();
#pragma unroll
        for (int kk = 0; kk < 16; kk++) {
            float4 av = *(const float4*)&As[kk][tr << 2];
            float4 b0 = *(const float4*)&Bs[kk][tc << 3];
            float4 b1 = *(const float4*)&Bs[kk][(tc << 3) + 4];
            float ar[4] = {av.x, av.y, av.z, av.w};
            float br[8] = {b0.x, b0.y, b0.z, b0.w, b1.x, b1.y, b1.z, b1.w};
#pragma unroll
            for (int i = 0; i < 4; i++)
#pragma unroll
                for (int j = 0; j < 8; j++) acc[i][j] = fmaf(ar[i], br[j], acc[i][j]);
        }
        __syncthreads();
    }

    float sg = 0.f;
    if (epi == 2) sg = 1.f / (1.f + __expf(-skipp[0]));
#pragma unroll
    for (int i = 0; i < 4; i++) {
        int gm = m0 + (tr << 2) + i;
        if (gm >= M) continue;
#pragma unroll
        for (int j = 0; j < 8; j++) {
            int col = (tc << 3) + j;
            float v = acc[i][j] + bias[col];
            if (epi == 1) v = fmaxf(v, 0.f);
            else if (epi == 2) v = sg * v + (1.f - sg) * Hprev[(size_t)gm * HID + col];
            C[(size_t)gm * HID + col] = v;
        }
    }
}

// ---------------- edge pass 1: logits + segment max ----------------
__global__ void edge_logits_kernel(const float* __restrict__ q, const float* __restrict__ kf,
                                   const int* __restrict__ src, const int* __restrict__ dst,
                                   const float* __restrict__ prior,
                                   float* __restrict__ logits, float* __restrict__ m, int E) {
    int t = blockIdx.x * blockDim.x + threadIdx.x;
    if (t >= E * NHEAD) return;
    int e = t >> 3;
    int h = t & 7;
    int sn = src[e];
    int dn = dst[e];
    const float4* qp = (const float4*)(q + (size_t)dn * HID + h * DH);
    const float4* kp = (const float4*)(kf + (size_t)sn * HID + h * DH);
    float acc = 0.f;
#pragma unroll
    for (int i = 0; i < 4; i++) {
        float4 a = qp[i], b = kp[i];
        acc = fmaf(a.x, b.x, acc); acc = fmaf(a.y, b.y, acc);
        acc = fmaf(a.z, b.z, acc); acc = fmaf(a.w, b.w, acc);
    }
    float lg = acc * prior[h] * 0.25f;  // 1/sqrt(16)
    logits[t] = lg;
    float* addr = m + (size_t)dn * NHEAD + h;
    if (__float_as_int(lg) >= 0)
        atomicMax((int*)addr, __float_as_int(lg));
    else
        atomicMin((unsigned int*)addr, __float_as_uint(lg));
}

// ---------------- edge pass 2: exp, segment sum, unnormalized weighted V scatter ----------------
__global__ void edge_accum_kernel(const float* __restrict__ vf,
                                  const int* __restrict__ src, const int* __restrict__ dst,
                                  const float* __restrict__ logits, const float* __restrict__ m,
                                  float* __restrict__ s, float* __restrict__ agg, int E) {
    int t = blockIdx.x * blockDim.x + threadIdx.x;
    if (t >= E * NHEAD) return;
    int e = t >> 3;
    int h = t & 7;
    int sn = src[e];
    int dn = dst[e];
    float w = __expf(logits[t] - m[(size_t)dn * NHEAD + h]);
    atomicAdd(s + (size_t)dn * NHEAD + h, w);
    const float4* vp = (const float4*)(vf + (size_t)sn * HID + h * DH);
    float* op = agg + (size_t)dn * HID + h * DH;
#pragma unroll
    for (int i = 0; i < 4; i++) {
        float4 v4 = vp[i];
        atomicAdd(op + i * 4 + 0, w * v4.x);
        atomicAdd(op + i * 4 + 1, w * v4.y);
        atomicAdd(op + i * 4 + 2, w * v4.z);
        atomicAdd(op + i * 4 + 3, w * v4.w);
    }
}

// ---------------- normalize: agg /= (s + 1e-16) ----------------
__global__ void norm_kernel(float* __restrict__ agg, const float* __restrict__ s, int n) {
    int t = blockIdx.x * blockDim.x + threadIdx.x;
    if (t >= n * HID) return;
    int node = t >> 7;
    int h = (t >> 4) & 7;
    agg[t] = agg[t] / (s[(size_t)node * NHEAD + h] + 1e-16f);
}

// ---------------- pair scoring: warp per pair, 256-dim dot ----------------
__global__ void pred_kernel(const float* __restrict__ f1a, const float* __restrict__ f1b,
                            const float* __restrict__ f2a, const float* __restrict__ f2b,
                            const int* __restrict__ mi, const int* __restrict__ di,
                            float* __restrict__ out, int P) {
    int gw = (blockIdx.x * blockDim.x + threadIdx.x) >> 5;
    int lane = threadIdx.x & 31;
    if (gw >= P) return;
    int mm = mi[gw];
    int dd = di[gw];
    float4 a0 = ((const float4*)(f1a + (size_t)mm * HID))[lane];
    float4 b0 = ((const float4*)(f2a + (size_t)dd * HID))[lane];
    float4 a1 = ((const float4*)(f1b + (size_t)mm * HID))[lane];
    float4 b1 = ((const float4*)(f2b + (size_t)dd * HID))[lane];
    float acc = a0.x * b0.x + a0.y * b0.y + a0.z * b0.z + a0.w * b0.w
              + a1.x * b1.x + a1.y * b1.y + a1.z * b1.z + a1.w * b1.w;
#pragma unroll
    for (int o = 16; o > 0; o >>= 1) acc += __shfl_xor_sync(0xFFFFFFFFu, acc, o);
    if (lane == 0) out[gw] = acc;
}

// ---------------- host orchestration ----------------
extern "C" void kernel_launch(void* const* d_in, const int* in_sizes, int n_in,
                              void* d_out, int out_size) {
    const float* x1    = (const float*)d_in[0];
    const float* x2    = (const float*)d_in[1];
    const int*   ei12  = (const int*)d_in[2];   // [2, E] src(N1), dst(N2)
    const int*   ei21  = (const int*)d_in[3];   // [2, E] src(N2), dst(N1)
    const int*   epair = (const int*)d_in[4];   // [2, P]
    const float* Win1  = (const float*)d_in[5];
    const float* bin1  = (const float*)d_in[6];
    const float* Win2  = (const float*)d_in[7];
    const float* bin2  = (const float*)d_in[8];
    const float* Wk    = (const float*)d_in[9];
    const float* bk    = (const float*)d_in[10];
    const float* Wq    = (const float*)d_in[11];
    const float* bq    = (const float*)d_in[12];
    const float* Wv    = (const float*)d_in[13];
    const float* bv    = (const float*)d_in[14];
    const float* Wa    = (const float*)d_in[15];
    const float* ba    = (const float*)d_in[16];
    const float* skip  = (const float*)d_in[17];
    const float* arel  = (const float*)d_in[18];
    const float* mrel  = (const float*)d_in[19];
    const float* prior = (const float*)d_in[20];
    float* out = (float*)d_out;

    void* p;
#define SYM(var, sym) cudaGetSymbolAddress(&p, sym); float* var = (float*)p;
    SYM(h1, g_h1) SYM(h2, g_h2)
    SYM(q1, g_q1) SYM(k1, g_k1) SYM(v1, g_v1)
    SYM(q2, g_q2) SYM(k2, g_k2) SYM(v2, g_v2)
    SYM(f1, g_f1) SYM(f2, g_f2)
    SYM(agg1, g_agg1) SYM(agg2, g_agg2)
    SYM(logits, g_logits)
    SYM(m1, g_m1) SYM(s1, g_s1) SYM(m2, g_m2) SYM(s2, g_s2)
    SYM(wfbase, g_Wf) SYM(bfbase, g_bf)
#undef SYM
    float* wf[4]; float* bf[4];
    for (int i = 0; i < 4; i++) { wf[i] = wfbase + i * HID * HID; bf[i] = bfbase + i * HID; }

    const int GEMM_GRID = (N1 + 63) / 64;        // 157 (N1 == N2)
    const int EH_BLOCKS = (E_EDGES * NHEAD + 255) / 256;
    const int NORM_BLOCKS = (N1 * HID + 255) / 256;
    const int PRED_BLOCKS = (P_PAIRS * 32 + 255) / 256;

    // input projections + relu
    gemm_kernel<<<GEMM_GRID, 256>>>(x1, Win1, bin1, nullptr, nullptr, h1, N1, F_IN, 0, 1);
    gemm_kernel<<<GEMM_GRID, 256>>>(x2, Win2, bin2, nullptr, nullptr, h2, N2, F_IN, 0, 1);

    const float* cur1 = h1;
    const float* cur2 = h2;

    for (int l = 0; l < 2; l++) {
        const int i0 = l * 2 + 0, i1 = l * 2 + 1;
        const float* Wk0 = Wk + (size_t)i0 * HID * HID; const float* bk0 = bk + (size_t)i0 * HID;
        const float* Wk1 = Wk + (size_t)i1 * HID * HID; const float* bk1 = bk + (size_t)i1 * HID;
        const float* Wv0 = Wv + (size_t)i0 * HID * HID; const float* bv0 = bv + (size_t)i0 * HID;
        const float* Wv1 = Wv + (size_t)i1 * HID * HID; const float* bv1 = bv + (size_t)i1 * HID;
        const float* Wq0 = Wq + (size_t)i0 * HID * HID; const float* bq0 = bq + (size_t)i0 * HID;
        const float* Wq1 = Wq + (size_t)i1 * HID * HID; const float* bq1 = bq + (size_t)i1 * HID;
        const float* ar0 = arel + (size_t)i0 * NHEAD * DH * DH;
        const float* ar1 = arel + (size_t)i1 * NHEAD * DH * DH;
        const float* mr0 = mrel + (size_t)i0 * NHEAD * DH * DH;
        const float* mr1 = mrel + (size_t)i1 * NHEAD * DH * DH;

        // fold relation matrices into K/V projection weights
        fold_kernel<<<64, 256>>>(Wk0, bk0, ar0, wf[0], bf[0]);
        fold_kernel<<<64, 256>>>(Wk1, bk1, ar1, wf[1], bf[1]);
        fold_kernel<<<64, 256>>>(Wv0, bv0, mr0, wf[2], bf[2]);
        fold_kernel<<<64, 256>>>(Wv1, bv1, mr1, wf[3], bf[3]);

        // projections
        gemm_kernel<<<GEMM_GRID, 256>>>(cur1, Wq0, bq0, nullptr, nullptr, q1, N1, HID, 0, 0);
        gemm_kernel<<<GEMM_GRID, 256>>>(cur2, Wq1, bq1, nullptr, nullptr, q2, N2, HID, 0, 0);
        gemm_kernel<<<GEMM_GRID, 256>>>(cur1, wf[0], bf[0], nullptr, nullptr, k1, N1, HID, 0, 0);
        gemm_kernel<<<GEMM_GRID, 256>>>(cur2, wf[1], bf[1], nullptr, nullptr, k2, N2, HID, 0, 0);
        gemm_kernel<<<GEMM_GRID, 256>>>(cur1, wf[2], bf[2], nullptr, nullptr, v1, N1, HID, 0, 0);
        gemm_kernel<<<GEMM_GRID, 256>>>(cur2, wf[3], bf[3], nullptr, nullptr, v2, N2, HID, 0, 0);

        // direction 0: n1 -> n2 (dst = n2)
        cudaMemsetAsync(m2, 0xFF, (size_t)N2 * NHEAD * 4);
        cudaMemsetAsync(s2, 0, (size_t)N2 * NHEAD * 4);
        cudaMemsetAsync(agg2, 0, (size_t)N2 * HID * 4);
        edge_logits_kernel<<<EH_BLOCKS, 256>>>(q2, k1, ei12, ei12 + E_EDGES,
                                               prior + i0 * NHEAD, logits, m2, E_EDGES);
        edge_accum_kernel<<<EH_BLOCKS, 256>>>(v1, ei12, ei12 + E_EDGES,
                                              logits, m2, s2, agg2, E_EDGES);
        norm_kernel<<<NORM_BLOCKS, 256>>>(agg2, s2, N2);

        // direction 1: n2 -> n1 (dst = n1)
        cudaMemsetAsync(m1, 0xFF, (size_t)N1 * NHEAD * 4);
        cudaMemsetAsync(s1, 0, (size_t)N1 * NHEAD * 4);
        cudaMemsetAsync(agg1, 0, (size_t)N1 * HID * 4);
        edge_logits_kernel<<<EH_BLOCKS, 256>>>(q1, k2, ei21, ei21 + E_EDGES,
                                               prior + i1 * NHEAD, logits, m1, E_EDGES);
        edge_accum_kernel<<<EH_BLOCKS, 256>>>(v2, ei21, ei21 + E_EDGES,
                                              logits, m1, s1, agg1, E_EDGES);
        norm_kernel<<<NORM_BLOCKS, 256>>>(agg1, s1, N1);

        // output: h = sigmoid(skip)*(gelu(agg) @ Wa + ba) + (1-sigmoid(skip))*h
        float* out1 = f1 + (size_t)l * N1 * HID;
        float* out2 = f2 + (size_t)l * N2 * HID;
        gemm_kernel<<<GEMM_GRID, 256>>>(agg1, Wa + (size_t)i0 * HID * HID, ba + (size_t)i0 * HID,
                                        cur1, skip + i0, out1, N1, HID, 1, 2);
        gemm_kernel<<<GEMM_GRID, 256>>>(agg2, Wa + (size_t)i1 * HID * HID, ba + (size_t)i1 * HID,
                                        cur2, skip + i1, out2, N2, HID, 1, 2);
        cur1 = out1;
        cur2 = out2;
    }

    // final gathered dot products over concatenated features
    pred_kernel<<<PRED_BLOCKS, 256>>>(f1, f1 + (size_t)N1 * HID,
                                      f2, f2 + (size_t)N2 * HID,
                                      epair, epair + P_PAIRS, out, P_PAIRS);
}

// round 2
// speedup vs baseline: 2.4399x; 2.4399x over previous
#include <cuda_runtime.h>
#include <cuda_bf16.h>
#include <math.h>

#define N1 10000
#define N2 10000
#define F_IN 256
#define E_EDGES 480000
#define P_PAIRS 200000
#define HID 128
#define NHEAD 8
#define DH 16

// ---------------- scratch (device globals; no dynamic alloc allowed) ----------------
__device__ float g_h1[N1 * HID];
__device__ float g_h2[N2 * HID];
__device__ float g_q1[N1 * HID];
__device__ float g_k1[N1 * HID];
__device__ float g_v1[N1 * HID];
__device__ float g_q2[N2 * HID];
__device__ float g_k2[N2 * HID];
__device__ float g_v2[N2 * HID];
__device__ float g_f1[2 * N1 * HID];
__device__ float g_f2[2 * N2 * HID];
__device__ float g_agg1[N1 * HID];
__device__ float g_agg2[N2 * HID];
__device__ float g_Wf[4][HID * HID];
__device__ float g_bf[4][HID];
// CSR: [0] = graph ei12 (dst in N2), [1] = graph ei21 (dst in N1)
__device__ int g_cnt[2][N1];
__device__ int g_off[2][N1 + 1];
__device__ int g_pos[2][N1];
__device__ int g_csr_src[2][E_EDGES];

// ---------------- helpers ----------------
__device__ __forceinline__ float gelu_tanh(float x) {
    const float c = 0.7978845608028654f;
    float t = tanhf(c * (x + 0.044715f * x * x * x));
    return 0.5f * x * (1.0f + t);
}

// ---------------- CSR build ----------------
__global__ void hist_kernel(const int* __restrict__ dst, int* __restrict__ cnt, int E) {
    int e = blockIdx.x * blockDim.x + threadIdx.x;
    if (e < E) atomicAdd(cnt + dst[e], 1);
}

// single-block exclusive scan over n counts -> off[0..n], pos copy
__global__ void scan_kernel(const int* __restrict__ cnt, int* __restrict__ off,
                            int* __restrict__ pos, int n) {
    __shared__ int sh[1024];
    __shared__ int base_s;
    if (threadIdx.x == 0) base_s = 0;
    __syncthreads();
    for (int c0 = 0; c0 < n; c0 += 1024) {
        int i = c0 + (int)threadIdx.x;
        int v = (i < n) ? cnt[i] : 0;
        sh[threadIdx.x] = v;
        __syncthreads();
        for (int o = 1; o < 1024; o <<= 1) {
            int t = (threadIdx.x >= o) ? sh[threadIdx.x - o] : 0;
            __syncthreads();
            sh[threadIdx.x] += t;
            __syncthreads();
        }
        int incl = sh[threadIdx.x];
        int excl = incl - v;
        int base = base_s;
        if (i < n) {
            off[i] = base + excl;
            pos[i] = base + excl;
            if (i == n - 1) off[n] = base + incl;
        }
        __syncthreads();
        if (threadIdx.x == 1023) base_s = base + sh[1023];
        __syncthreads();
    }
}

__global__ void scatter_kernel(const int* __restrict__ src, const int* __restrict__ dst,
                               int* __restrict__ pos, int* __restrict__ csr_src, int E) {
    int e = blockIdx.x * blockDim.x + threadIdx.x;
    if (e >= E) return;
    int p = atomicAdd(pos + dst[e], 1);
    csr_src[p] = src[e];
}

// ---------------- fold arel/mrel into projection weights ----------------
__global__ void fold_kernel(const float* __restrict__ W, const float* __restrict__ b,
                            const float* __restrict__ rel,
                            float* __restrict__ Wf, float* __restrict__ bf) {
    int t = blockIdx.x * blockDim.x + threadIdx.x;
    if (t >= HID * HID) return;
    int row = t >> 7;
    int col = t & 127;
    int h = col >> 4;
    int eo = col & 15;
    const float* relh = rel + h * (DH * DH);
    const float* wrow = W + row * HID + h * DH;
    float acc = 0.f;
#pragma unroll
    for (int d = 0; d < DH; d++) acc = fmaf(wrow[d], relh[d * DH + eo], acc);
    Wf[t] = acc;
    if (row == 0) {
        const float* brow = b + h * DH;
        float accb = 0.f;
#pragma unroll
        for (int d = 0; d < DH; d++) accb = fmaf(brow[d], relh[d * DH + eo], accb);
        bf[col] = accb;
    }
}

// ---------------- GEMM: C[M,128] = epi( actA(A[M,K]) @ B[K,128] + bias ) ----------------
__global__ void __launch_bounds__(256, 2) gemm_kernel(
    const float* __restrict__ A, const float* __restrict__ B,
    const float* __restrict__ bias, const float* __restrict__ Hprev,
    const float* __restrict__ skipp, float* __restrict__ C,
    int M, int K, int geluA, int epi) {
    __shared__ float As[16][68];
    __shared__ float Bs[16][128];

    const int tid = threadIdx.x;
    const int m0 = blockIdx.x * 64;
    const int tr = tid >> 4;
    const int tc = tid & 15;
    const int arow = tid >> 2;
    const int akol = (tid & 3) << 2;
    const int brow = tid >> 5;
    const int bcol = (tid & 31) << 2;

    float acc[4][8];
#pragma unroll
    for (int i = 0; i < 4; i++)
#pragma unroll
        for (int j = 0; j < 8; j++) acc[i][j] = 0.f;

    const int gr = m0 + arow;
    const float* Aptr = A + (size_t)gr * K;

    for (int k0 = 0; k0 < K; k0 += 16) {
        float4 a4 = make_float4(0.f, 0.f, 0.f, 0.f);
        if (gr < M) a4 = *(const float4*)(Aptr + k0 + akol);
        if (geluA) {
            a4.x = gelu_tanh(a4.x); a4.y = gelu_tanh(a4.y);
            a4.z = gelu_tanh(a4.z); a4.w = gelu_tanh(a4.w);
        }
        As[akol + 0][arow] = a4.x;
        As[akol + 1][arow] = a4.y;
        As[akol + 2][arow] = a4.z;
        As[akol + 3][arow] = a4.w;
        *(float4*)&Bs[brow][bcol]     = *(const float4*)(B + (size_t)(k0 + brow) * HID + bcol);
        *(float4*)&Bs[brow + 8][bcol] = *(const float4*)(B + (size_t)(k0 + brow + 8) * HID + bcol);
        __syncthreads();
#pragma unroll
        for (int kk = 0; kk < 16; kk++) {
            float4 av = *(const float4*)&As[kk][tr << 2];
            float4 b0 = *(const float4*)&Bs[kk][tc << 3];
            float4 b1 = *(const float4*)&Bs[kk][(tc << 3) + 4];
            float ar[4] = {av.x, av.y, av.z, av.w};
            float br[8] = {b0.x, b0.y, b0.z, b0.w, b1.x, b1.y, b1.z, b1.w};
#pragma unroll
            for (int i = 0; i < 4; i++)
#pragma unroll
                for (int j = 0; j < 8; j++) acc[i][j] = fmaf(ar[i], br[j], acc[i][j]);
        }
        __syncthreads();
    }

    float sg = 0.f;
    if (epi == 2) sg = 1.f / (1.f + __expf(-skipp[0]));
#pragma unroll
    for (int i = 0; i < 4; i++) {
        int gm = m0 + (tr << 2) + i;
        if (gm >= M) continue;
#pragma unroll
        for (int j = 0; j < 8; j++) {
            int col = (tc << 3) + j;
            float v = acc[i][j] + bias[col];
            if (epi == 1) v = fmaxf(v, 0.f);
            else if (epi == 2) v = sg * v + (1.f - sg) * Hprev[(size_t)gm * HID + col];
            C[(size_t)gm * HID + col] = v;
        }
    }
}

// ---------------- attention: warp per dst node, online softmax, no atomics ----------------
__global__ void __launch_bounds__(256) attn_kernel(
    const float* __restrict__ q, const float* __restrict__ kf, const float* __restrict__ vf,
    const int* __restrict__ csr_src, const int* __restrict__ off,
    const float* __restrict__ prior, float* __restrict__ agg, int n) {
    int node = blockIdx.x * 8 + (threadIdx.x >> 5);
    if (node >= n) return;
    int lane = threadIdx.x & 31;
    int h = lane >> 2;

    int beg = off[node];
    int end = off[node + 1];
    float4 qv = ((const float4*)(q + (size_t)node * HID))[lane];
    float pr = prior[h] * 0.25f;  // 1/sqrt(16)

    float m = -INFINITY, s = 0.f;
    float ax = 0.f, ay = 0.f, az = 0.f, aw = 0.f;

    for (int i = beg; i < end; i++) {
        int sn = csr_src[i];
        float4 kv = ((const float4*)(kf + (size_t)sn * HID))[lane];
        float4 vv = ((const float4*)(vf + (size_t)sn * HID))[lane];
        float d = qv.x * kv.x + qv.y * kv.y + qv.z * kv.z + qv.w * kv.w;
        d += __shfl_xor_sync(0xFFFFFFFFu, d, 1);
        d += __shfl_xor_sync(0xFFFFFFFFu, d, 2);
        float lg = d * pr;
        float nm = fmaxf(m, lg);
        float c = __expf(m - nm);   // first iter: exp(-inf) = 0
        float w = __expf(lg - nm);
        m = nm;
        s = s * c + w;
        ax = ax * c + w * vv.x;
        ay = ay * c + w * vv.y;
        az = az * c + w * vv.z;
        aw = aw * c + w * vv.w;
    }
    float inv = 1.f / (s + 1e-16f);
    ((float4*)(agg + (size_t)node * HID))[lane] = make_float4(ax * inv, ay * inv, az * inv, aw * inv);
}

// ---------------- pair scoring ----------------
__global__ void pred_kernel(const float* __restrict__ f1a, const float* __restrict__ f1b,
                            const float* __restrict__ f2a, const float* __restrict__ f2b,
                            const int* __restrict__ mi, const int* __restrict__ di,
                            float* __restrict__ out, int P) {
    int gw = (blockIdx.x * blockDim.x + threadIdx.x) >> 5;
    int lane = threadIdx.x & 31;
    if (gw >= P) return;
    int mm = mi[gw];
    int dd = di[gw];
    float4 a0 = ((const float4*)(f1a + (size_t)mm * HID))[lane];
    float4 b0 = ((const float4*)(f2a + (size_t)dd * HID))[lane];
    float4 a1 = ((const float4*)(f1b + (size_t)mm * HID))[lane];
    float4 b1 = ((const float4*)(f2b + (size_t)dd * HID))[lane];
    float acc = a0.x * b0.x + a0.y * b0.y + a0.z * b0.z + a0.w * b0.w
              + a1.x * b1.x + a1.y * b1.y + a1.z * b1.z + a1.w * b1.w;
#pragma unroll
    for (int o = 16; o > 0; o >>= 1) acc += __shfl_xor_sync(0xFFFFFFFFu, acc, o);
    if (lane == 0) out[gw] = acc;
}

// ---------------- host orchestration ----------------
extern "C" void kernel_launch(void* const* d_in, const int* in_sizes, int n_in,
                              void* d_out, int out_size) {
    const float* x1    = (const float*)d_in[0];
    const float* x2    = (const float*)d_in[1];
    const int*   ei12  = (const int*)d_in[2];
    const int*   ei21  = (const int*)d_in[3];
    const int*   epair = (const int*)d_in[4];
    const float* Win1  = (const float*)d_in[5];
    const float* bin1  = (const float*)d_in[6];
    const float* Win2  = (const float*)d_in[7];
    const float* bin2  = (const float*)d_in[8];
    const float* Wk    = (const float*)d_in[9];
    const float* bk    = (const float*)d_in[10];
    const float* Wq    = (const float*)d_in[11];
    const float* bq    = (const float*)d_in[12];
    const float* Wv    = (const float*)d_in[13];
    const float* bv    = (const float*)d_in[14];
    const float* Wa    = (const float*)d_in[15];
    const float* ba    = (const float*)d_in[16];
    const float* skip  = (const float*)d_in[17];
    const float* arel  = (const float*)d_in[18];
    const float* mrel  = (const float*)d_in[19];
    const float* prior = (const float*)d_in[20];
    float* out = (float*)d_out;

    void* p;
#define SYMF(var, sym) cudaGetSymbolAddress(&p, sym); float* var = (float*)p;
#define SYMI(var, sym) cudaGetSymbolAddress(&p, sym); int* var = (int*)p;
    SYMF(h1, g_h1) SYMF(h2, g_h2)
    SYMF(q1, g_q1) SYMF(k1, g_k1) SYMF(v1, g_v1)
    SYMF(q2, g_q2) SYMF(k2, g_k2) SYMF(v2, g_v2)
    SYMF(f1, g_f1) SYMF(f2, g_f2)
    SYMF(agg1, g_agg1) SYMF(agg2, g_agg2)
    SYMF(wfbase, g_Wf) SYMF(bfbase, g_bf)
    SYMI(cnt, g_cnt) SYMI(off, g_off) SYMI(pos, g_pos) SYMI(csr, g_csr_src)
#undef SYMF
#undef SYMI
    float* wf[4]; float* bf[4];
    for (int i = 0; i < 4; i++) { wf[i] = wfbase + i * HID * HID; bf[i] = bfbase + i * HID; }
    int* cnt12 = cnt;            int* cnt21 = cnt + N1;
    int* off12 = off;            int* off21 = off + (N1 + 1);
    int* pos12 = pos;            int* pos21 = pos + N1;
    int* csr12 = csr;            int* csr21 = csr + E_EDGES;

    const int GEMM_GRID = (N1 + 63) / 64;
    const int E_BLOCKS = (E_EDGES + 255) / 256;
    const int ATTN_GRID = (N1 + 7) / 8;
    const int PRED_BLOCKS = (P_PAIRS * 32 + 255) / 256;

    // ---- build CSR (dst-major) for both edge sets; indices launch-invariant ----
    cudaMemsetAsync(cnt12, 0, (size_t)2 * N1 * 4);
    hist_kernel<<<E_BLOCKS, 256>>>(ei12 + E_EDGES, cnt12, E_EDGES);   // dst in N2
    hist_kernel<<<E_BLOCKS, 256>>>(ei21 + E_EDGES, cnt21, E_EDGES);   // dst in N1
    scan_kernel<<<1, 1024>>>(cnt12, off12, pos12, N2);
    scan_kernel<<<1, 1024>>>(cnt21, off21, pos21, N1);
    scatter_kernel<<<E_BLOCKS, 256>>>(ei12, ei12 + E_EDGES, pos12, csr12, E_EDGES);
    scatter_kernel<<<E_BLOCKS, 256>>>(ei21, ei21 + E_EDGES, pos21, csr21, E_EDGES);

    // ---- input projections + relu ----
    gemm_kernel<<<GEMM_GRID, 256>>>(x1, Win1, bin1, nullptr, nullptr, h1, N1, F_IN, 0, 1);
    gemm_kernel<<<GEMM_GRID, 256>>>(x2, Win2, bin2, nullptr, nullptr, h2, N2, F_IN, 0, 1);

    const float* cur1 = h1;
    const float* cur2 = h2;

    for (int l = 0; l < 2; l++) {
        const int i0 = l * 2 + 0, i1 = l * 2 + 1;
        const float* Wk0 = Wk + (size_t)i0 * HID * HID; const float* bk0 = bk + (size_t)i0 * HID;
        const float* Wk1 = Wk + (size_t)i1 * HID * HID; const float* bk1 = bk + (size_t)i1 * HID;
        const float* Wv0 = Wv + (size_t)i0 * HID * HID; const float* bv0 = bv + (size_t)i0 * HID;
        const float* Wv1 = Wv + (size_t)i1 * HID * HID; const float* bv1 = bv + (size_t)i1 * HID;
        const float* Wq0 = Wq + (size_t)i0 * HID * HID; const float* bq0 = bq + (size_t)i0 * HID;
        const float* Wq1 = Wq + (size_t)i1 * HID * HID; const float* bq1 = bq + (size_t)i1 * HID;
        const float* ar0 = arel + (size_t)i0 * NHEAD * DH * DH;
        const float* ar1 = arel + (size_t)i1 * NHEAD * DH * DH;
        const float* mr0 = mrel + (size_t)i0 * NHEAD * DH * DH;
        const float* mr1 = mrel + (size_t)i1 * NHEAD * DH * DH;

        fold_kernel<<<64, 256>>>(Wk0, bk0, ar0, wf[0], bf[0]);
        fold_kernel<<<64, 256>>>(Wk1, bk1, ar1, wf[1], bf[1]);
        fold_kernel<<<64, 256>>>(Wv0, bv0, mr0, wf[2], bf[2]);
        fold_kernel<<<64, 256>>>(Wv1, bv1, mr1, wf[3], bf[3]);

        gemm_kernel<<<GEMM_GRID, 256>>>(cur1, Wq0, bq0, nullptr, nullptr, q1, N1, HID, 0, 0);
        gemm_kernel<<<GEMM_GRID, 256>>>(cur2, Wq1, bq1, nullptr, nullptr, q2, N2, HID, 0, 0);
        gemm_kernel<<<GEMM_GRID, 256>>>(cur1, wf[0], bf[0], nullptr, nullptr, k1, N1, HID, 0, 0);
        gemm_kernel<<<GEMM_GRID, 256>>>(cur2, wf[1], bf[1], nullptr, nullptr, k2, N2, HID, 0, 0);
        gemm_kernel<<<GEMM_GRID, 256>>>(cur1, wf[2], bf[2], nullptr, nullptr, v1, N1, HID, 0, 0);
        gemm_kernel<<<GEMM_GRID, 256>>>(cur2, wf[3], bf[3], nullptr, nullptr, v2, N2, HID, 0, 0);

        // dst = n2 (sources in n1); dst = n1 (sources in n2)
        attn_kernel<<<ATTN_GRID, 256>>>(q2, k1, v1, csr12, off12, prior + i0 * NHEAD, agg2, N2);
        attn_kernel<<<ATTN_GRID, 256>>>(q1, k2, v2, csr21, off21, prior + i1 * NHEAD, agg1, N1);

        float* out1 = f1 + (size_t)l * N1 * HID;
        float* out2 = f2 + (size_t)l * N2 * HID;
        gemm_kernel<<<GEMM_GRID, 256>>>(agg1, Wa + (size_t)i0 * HID * HID, ba + (size_t)i0 * HID,
                                        cur1, skip + i0, out1, N1, HID, 1, 2);
        gemm_kernel<<<GEMM_GRID, 256>>>(agg2, Wa + (size_t)i1 * HID * HID, ba + (size_t)i1 * HID,
                                        cur2, skip + i1, out2, N2, HID, 1, 2);
        cur1 = out1;
        cur2 = out2;
    }

    pred_kernel<<<PRED_BLOCKS, 256>>>(f1, f1 + (size_t)N1 * HID,
                                      f2, f2 + (size_t)N2 * HID,
                                      epair, epair + P_PAIRS, out, P_PAIRS);
}

// round 3
// speedup vs baseline: 3.5661x; 1.4616x over previous
#include <cuda_runtime.h>
#include <cuda_bf16.h>
#include <math.h>

#define N1 10000
#define N2 10000
#define F_IN 256
#define E_EDGES 480000
#define P_PAIRS 200000
#define HID 128
#define NHEAD 8
#define DH 16

// ---------------- scratch (device globals) ----------------
__device__ float g_h1[N1 * HID];
__device__ float g_h2[N2 * HID];
__device__ float g_q1[N1 * HID];
__device__ float g_k1[N1 * HID];
__device__ float g_v1[N1 * HID];
__device__ float g_q2[N2 * HID];
__device__ float g_k2[N2 * HID];
__device__ float g_v2[N2 * HID];
__device__ float g_f1[2 * N1 * HID];
__device__ float g_f2[2 * N2 * HID];
__device__ float g_agg1[N1 * HID];
__device__ float g_agg2[N2 * HID];
__device__ float g_Wf[4][HID * HID];
__device__ float g_bf[4][HID];
__device__ int g_cnt[2][N1];
__device__ int g_off[2][N1 + 1];
__device__ int g_pos[2][N1];
__device__ int g_csr_src[2][E_EDGES];

// ---------------- arg structs for batched launches ----------------
struct GemmArgs { const float* A; const float* B; const float* bias;
                  const float* Hprev; const float* skipp; float* C; };
struct GemmBatch { GemmArgs g[6]; };
struct FoldArgs { const float* W; const float* b; const float* rel; float* Wf; float* bf; };
struct FoldBatch { FoldArgs f[4]; };
struct AttnArgs { const float* q; const float* k; const float* v;
                  const int* csr; const int* off; const float* prior; float* agg; };
struct AttnBatch { AttnArgs a[2]; };

__device__ __forceinline__ float gelu_tanh(float x) {
    const float c = 0.7978845608028654f;
    float t = tanhf(c * (x + 0.044715f * x * x * x));
    return 0.5f * x * (1.0f + t);
}

// ---------------- CSR build ----------------
__global__ void hist2_kernel(const int* __restrict__ dst0, int* __restrict__ cnt0,
                             const int* __restrict__ dst1, int* __restrict__ cnt1, int E) {
    int t = blockIdx.x * blockDim.x + threadIdx.x;
    if (t < E) atomicAdd(cnt0 + dst0[t], 1);
    else if (t < 2 * E) atomicAdd(cnt1 + dst1[t - E], 1);
}

// warp-shuffle chunked scan; 2 blocks, one per graph
__global__ void scan2_kernel(const int* __restrict__ cnt0, int* __restrict__ off0, int* __restrict__ pos0,
                             const int* __restrict__ cnt1, int* __restrict__ off1, int* __restrict__ pos1,
                             int n) {
    const int* cnt = blockIdx.x ? cnt1 : cnt0;
    int* off = blockIdx.x ? off1 : off0;
    int* pos = blockIdx.x ? pos1 : pos0;
    __shared__ int warpsum[32];
    __shared__ int base_s;
    int tid = threadIdx.x, lane = tid & 31, wid = tid >> 5;
    if (tid == 0) base_s = 0;
    __syncthreads();
    for (int c0 = 0; c0 < n; c0 += 1024) {
        int i = c0 + tid;
        int v = (i < n) ? cnt[i] : 0;
        int x = v;
#pragma unroll
        for (int o = 1; o < 32; o <<= 1) {
            int t = __shfl_up_sync(0xFFFFFFFFu, x, o);
            if (lane >= o) x += t;
        }
        if (lane == 31) warpsum[wid] = x;
        __syncthreads();
        if (wid == 0) {
            int s = warpsum[lane];
#pragma unroll
            for (int o = 1; o < 32; o <<= 1) {
                int t = __shfl_up_sync(0xFFFFFFFFu, s, o);
                if (lane >= o) s += t;
            }
            warpsum[lane] = s;
        }
        __syncthreads();
        int add = (wid > 0) ? warpsum[wid - 1] : 0;
        int incl = x + add + base_s;
        int excl = incl - v;
        if (i < n) {
            off[i] = excl;
            pos[i] = excl;
            if (i == n - 1) off[n] = incl;
        }
        __syncthreads();
        if (tid == 1023) base_s = incl;
        __syncthreads();
    }
}

__global__ void scatter2_kernel(const int* __restrict__ src0, const int* __restrict__ dst0,
                                int* __restrict__ pos0, int* __restrict__ csr0,
                                const int* __restrict__ src1, const int* __restrict__ dst1,
                                int* __restrict__ pos1, int* __restrict__ csr1, int E) {
    int t = blockIdx.x * blockDim.x + threadIdx.x;
    if (t < E) {
        int p = atomicAdd(pos0 + dst0[t], 1);
        csr0[p] = src0[t];
    } else if (t < 2 * E) {
        int e = t - E;
        int p = atomicAdd(pos1 + dst1[e], 1);
        csr1[p] = src1[e];
    }
}

// ---------------- fold arel/mrel into projection weights (batched x4) ----------------
__global__ void fold_kernel(FoldBatch fb) {
    FoldArgs fa = fb.f[blockIdx.y];
    int t = blockIdx.x * blockDim.x + threadIdx.x;
    if (t >= HID * HID) return;
    int row = t >> 7;
    int col = t & 127;
    int h = col >> 4;
    int eo = col & 15;
    const float* relh = fa.rel + h * (DH * DH);
    const float* wrow = fa.W + row * HID + h * DH;
    float acc = 0.f;
#pragma unroll
    for (int d = 0; d < DH; d++) acc = fmaf(wrow[d], relh[d * DH + eo], acc);
    fa.Wf[t] = acc;
    if (row == 0) {
        const float* brow = fa.b + h * DH;
        float accb = 0.f;
#pragma unroll
        for (int d = 0; d < DH; d++) accb = fmaf(brow[d], relh[d * DH + eo], accb);
        fa.bf[col] = accb;
    }
}

// ---------------- GEMM: C[M,128] = epi( actA(A[M,K]) @ B[K,128] + bias ), batched ----------------
__global__ void __launch_bounds__(256, 4) gemm_kernel(
    GemmBatch batch, int M, int K, int geluA, int epi) {
    GemmArgs ga = batch.g[blockIdx.y];
    const float* __restrict__ A = ga.A;
    const float* __restrict__ B = ga.B;

    __shared__ float As[16][68];
    __shared__ float Bs[16][128];

    const int tid = threadIdx.x;
    const int m0 = blockIdx.x * 64;
    const int tr = tid >> 4;
    const int tc = tid & 15;
    const int arow = tid >> 2;
    const int akol = (tid & 3) << 2;
    const int brow = tid >> 5;
    const int bcol = (tid & 31) << 2;

    float acc[4][8];
#pragma unroll
    for (int i = 0; i < 4; i++)
#pragma unroll
        for (int j = 0; j < 8; j++) acc[i][j] = 0.f;

    const int gr = m0 + arow;
    const float* Aptr = A + (size_t)gr * K;

    for (int k0 = 0; k0 < K; k0 += 16) {
        float4 a4 = make_float4(0.f, 0.f, 0.f, 0.f);
        if (gr < M) a4 = *(const float4*)(Aptr + k0 + akol);
        if (geluA) {
            a4.x = gelu_tanh(a4.x); a4.y = gelu_tanh(a4.y);
            a4.z = gelu_tanh(a4.z); a4.w = gelu_tanh(a4.w);
        }
        As[akol + 0][arow] = a4.x;
        As[akol + 1][arow] = a4.y;
        As[akol + 2][arow] = a4.z;
        As[akol + 3][arow] = a4.w;
        *(float4*)&Bs[brow][bcol]     = *(const float4*)(B + (size_t)(k0 + brow) * HID + bcol);
        *(float4*)&Bs[brow + 8][bcol] = *(const float4*)(B + (size_t)(k0 + brow + 8) * HID + bcol);
        __syncthreads();
#pragma unroll
        for (int kk = 0; kk < 16; kk++) {
            float4 av = *(const float4*)&As[kk][tr << 2];
            float a0 = av.x, a1 = av.y, a2 = av.z, a3 = av.w;
            float4 b0 = *(const float4*)&Bs[kk][tc << 3];
#define FMA4(J, BV) \
            acc[0][J] = fmaf(a0, BV, acc[0][J]); acc[1][J] = fmaf(a1, BV, acc[1][J]); \
            acc[2][J] = fmaf(a2, BV, acc[2][J]); acc[3][J] = fmaf(a3, BV, acc[3][J]);
            FMA4(0, b0.x) FMA4(1, b0.y) FMA4(2, b0.z) FMA4(3, b0.w)
            float4 b1 = *(const float4*)&Bs[kk][(tc << 3) + 4];
            FMA4(4, b1.x) FMA4(5, b1.y) FMA4(6, b1.z) FMA4(7, b1.w)
#undef FMA4
        }
        __syncthreads();
    }

    float sg = 0.f;
    if (epi == 2) sg = 1.f / (1.f + __expf(-ga.skipp[0]));
#pragma unroll
    for (int i = 0; i < 4; i++) {
        int gm = m0 + (tr << 2) + i;
        if (gm >= M) continue;
#pragma unroll
        for (int j = 0; j < 8; j++) {
            int col = (tc << 3) + j;
            float v = acc[i][j] + ga.bias[col];
            if (epi == 1) v = fmaxf(v, 0.f);
            else if (epi == 2) v = sg * v + (1.f - sg) * ga.Hprev[(size_t)gm * HID + col];
            ga.C[(size_t)gm * HID + col] = v;
        }
    }
}

// ---------------- attention: warp/dst node, online softmax, 2-edge unroll, batched x2 ----------------
__global__ void __launch_bounds__(256) attn_kernel(AttnBatch ab, int n) {
    AttnArgs aa = ab.a[blockIdx.y];
    int node = blockIdx.x * 8 + (threadIdx.x >> 5);
    if (node >= n) return;
    int lane = threadIdx.x & 31;
    int h = lane >> 2;

    int beg = aa.off[node];
    int end = aa.off[node + 1];
    float4 qv = ((const float4*)(aa.q + (size_t)node * HID))[lane];
    float pr = aa.prior[h] * 0.25f;  // 1/sqrt(16)

    float m = -INFINITY, s = 0.f;
    float ax = 0.f, ay = 0.f, az = 0.f, aw = 0.f;

    int i = beg;
    for (; i + 1 < end; i += 2) {
        int sn0 = aa.csr[i];
        int sn1 = aa.csr[i + 1];
        float4 k0 = ((const float4*)(aa.k + (size_t)sn0 * HID))[lane];
        float4 v0 = ((const float4*)(aa.v + (size_t)sn0 * HID))[lane];
        float4 k1 = ((const float4*)(aa.k + (size_t)sn1 * HID))[lane];
        float4 v1 = ((const float4*)(aa.v + (size_t)sn1 * HID))[lane];
        float d0 = qv.x * k0.x + qv.y * k0.y + qv.z * k0.z + qv.w * k0.w;
        float d1 = qv.x * k1.x + qv.y * k1.y + qv.z * k1.z + qv.w * k1.w;
        d0 += __shfl_xor_sync(0xFFFFFFFFu, d0, 1);
        d1 += __shfl_xor_sync(0xFFFFFFFFu, d1, 1);
        d0 += __shfl_xor_sync(0xFFFFFFFFu, d0, 2);
        d1 += __shfl_xor_sync(0xFFFFFFFFu, d1, 2);
        float lg0 = d0 * pr, lg1 = d1 * pr;
        float nm = fmaxf(m, fmaxf(lg0, lg1));
        float c = __expf(m - nm);
        float w0 = __expf(lg0 - nm);
        float w1 = __expf(lg1 - nm);
        m = nm;
        s = s * c + w0 + w1;
        ax = ax * c + w0 * v0.x + w1 * v1.x;
        ay = ay * c + w0 * v0.y + w1 * v1.y;
        az = az * c + w0 * v0.z + w1 * v1.z;
        aw = aw * c + w0 * v0.w + w1 * v1.w;
    }
    if (i < end) {
        int sn = aa.csr[i];
        float4 kv = ((const float4*)(aa.k + (size_t)sn * HID))[lane];
        float4 vv = ((const float4*)(aa.v + (size_t)sn * HID))[lane];
        float d = qv.x * kv.x + qv.y * kv.y + qv.z * kv.z + qv.w * kv.w;
        d += __shfl_xor_sync(0xFFFFFFFFu, d, 1);
        d += __shfl_xor_sync(0xFFFFFFFFu, d, 2);
        float lg = d * pr;
        float nm = fmaxf(m, lg);
        float c = __expf(m - nm);
        float w = __expf(lg - nm);
        m = nm;
        s = s * c + w;
        ax = ax * c + w * vv.x;
        ay = ay * c + w * vv.y;
        az = az * c + w * vv.z;
        aw = aw * c + w * vv.w;
    }
    float inv = 1.f / (s + 1e-16f);
    ((float4*)(aa.agg + (size_t)node * HID))[lane] = make_float4(ax * inv, ay * inv, az * inv, aw * inv);
}

// ---------------- pair scoring ----------------
__global__ void pred_kernel(const float* __restrict__ f1a, const float* __restrict__ f1b,
                            const float* __restrict__ f2a, const float* __restrict__ f2b,
                            const int* __restrict__ mi, const int* __restrict__ di,
                            float* __restrict__ out, int P) {
    int gw = (blockIdx.x * blockDim.x + threadIdx.x) >> 5;
    int lane = threadIdx.x & 31;
    if (gw >= P) return;
    int mm = mi[gw];
    int dd = di[gw];
    float4 a0 = ((const float4*)(f1a + (size_t)mm * HID))[lane];
    float4 b0 = ((const float4*)(f2a + (size_t)dd * HID))[lane];
    float4 a1 = ((const float4*)(f1b + (size_t)mm * HID))[lane];
    float4 b1 = ((const float4*)(f2b + (size_t)dd * HID))[lane];
    float acc = a0.x * b0.x + a0.y * b0.y + a0.z * b0.z + a0.w * b0.w
              + a1.x * b1.x + a1.y * b1.y + a1.z * b1.z + a1.w * b1.w;
#pragma unroll
    for (int o = 16; o > 0; o >>= 1) acc += __shfl_xor_sync(0xFFFFFFFFu, acc, o);
    if (lane == 0) out[gw] = acc;
}

// ---------------- host orchestration ----------------
extern "C" void kernel_launch(void* const* d_in, const int* in_sizes, int n_in,
                              void* d_out, int out_size) {
    const float* x1    = (const float*)d_in[0];
    const float* x2    = (const float*)d_in[1];
    const int*   ei12  = (const int*)d_in[2];
    const int*   ei21  = (const int*)d_in[3];
    const int*   epair = (const int*)d_in[4];
    const float* Win1  = (const float*)d_in[5];
    const float* bin1  = (const float*)d_in[6];
    const float* Win2  = (const float*)d_in[7];
    const float* bin2  = (const float*)d_in[8];
    const float* Wk    = (const float*)d_in[9];
    const float* bk    = (const float*)d_in[10];
    const float* Wq    = (const float*)d_in[11];
    const float* bq    = (const float*)d_in[12];
    const float* Wv    = (const float*)d_in[13];
    const float* bv    = (const float*)d_in[14];
    const float* Wa    = (const float*)d_in[15];
    const float* ba    = (const float*)d_in[16];
    const float* skip  = (const float*)d_in[17];
    const float* arel  = (const float*)d_in[18];
    const float* mrel  = (const float*)d_in[19];
    const float* prior = (const float*)d_in[20];
    float* out = (float*)d_out;

    void* p;
#define SYMF(var, sym) cudaGetSymbolAddress(&p, sym); float* var = (float*)p;
#define SYMI(var, sym) cudaGetSymbolAddress(&p, sym); int* var = (int*)p;
    SYMF(h1, g_h1) SYMF(h2, g_h2)
    SYMF(q1, g_q1) SYMF(k1, g_k1) SYMF(v1, g_v1)
    SYMF(q2, g_q2) SYMF(k2, g_k2) SYMF(v2, g_v2)
    SYMF(f1, g_f1) SYMF(f2, g_f2)
    SYMF(agg1, g_agg1) SYMF(agg2, g_agg2)
    SYMF(wfbase, g_Wf) SYMF(bfbase, g_bf)
    SYMI(cnt, g_cnt) SYMI(off, g_off) SYMI(pos, g_pos) SYMI(csr, g_csr_src)
#undef SYMF
#undef SYMI
    float* wf[4]; float* bf[4];
    for (int i = 0; i < 4; i++) { wf[i] = wfbase + i * HID * HID; bf[i] = bfbase + i * HID; }
    int* cnt12 = cnt;  int* cnt21 = cnt + N1;
    int* off12 = off;  int* off21 = off + (N1 + 1);
    int* pos12 = pos;  int* pos21 = pos + N1;
    int* csr12 = csr;  int* csr21 = csr + E_EDGES;

    const int GEMM_GRID = (N1 + 63) / 64;
    const int E2_BLOCKS = (2 * E_EDGES + 255) / 256;
    const int ATTN_GRID = (N1 + 7) / 8;
    const int PRED_BLOCKS = (P_PAIRS * 32 + 255) / 256;

    // ---- CSR build (both graphs per launch) ----
    cudaMemsetAsync(cnt12, 0, (size_t)2 * N1 * 4);
    hist2_kernel<<<E2_BLOCKS, 256>>>(ei12 + E_EDGES, cnt12, ei21 + E_EDGES, cnt21, E_EDGES);
    scan2_kernel<<<2, 1024>>>(cnt12, off12, pos12, cnt21, off21, pos21, N1);
    scatter2_kernel<<<E2_BLOCKS, 256>>>(ei12, ei12 + E_EDGES, pos12, csr12,
                                        ei21, ei21 + E_EDGES, pos21, csr21, E_EDGES);

    // ---- input projections + relu (batched x2) ----
    {
        GemmBatch gb = {};
        gb.g[0] = {x1, Win1, bin1, nullptr, nullptr, h1};
        gb.g[1] = {x2, Win2, bin2, nullptr, nullptr, h2};
        gemm_kernel<<<dim3(GEMM_GRID, 2), 256>>>(gb, N1, F_IN, 0, 1);
    }

    const float* cur1 = h1;
    const float* cur2 = h2;

    for (int l = 0; l < 2; l++) {
        const int i0 = l * 2 + 0, i1 = l * 2 + 1;
        {
            FoldBatch fb;
            fb.f[0] = {Wk + (size_t)i0 * HID * HID, bk + (size_t)i0 * HID,
                       arel + (size_t)i0 * NHEAD * DH * DH, wf[0], bf[0]};
            fb.f[1] = {Wk + (size_t)i1 * HID * HID, bk + (size_t)i1 * HID,
                       arel + (size_t)i1 * NHEAD * DH * DH, wf[1], bf[1]};
            fb.f[2] = {Wv + (size_t)i0 * HID * HID, bv + (size_t)i0 * HID,
                       mrel + (size_t)i0 * NHEAD * DH * DH, wf[2], bf[2]};
            fb.f[3] = {Wv + (size_t)i1 * HID * HID, bv + (size_t)i1 * HID,
                       mrel + (size_t)i1 * NHEAD * DH * DH, wf[3], bf[3]};
            fold_kernel<<<dim3(64, 4), 256>>>(fb);
        }
        {
            GemmBatch gb;
            gb.g[0] = {cur1, Wq + (size_t)i0 * HID * HID, bq + (size_t)i0 * HID, nullptr, nullptr, q1};
            gb.g[1] = {cur2, Wq + (size_t)i1 * HID * HID, bq + (size_t)i1 * HID, nullptr, nullptr, q2};
            gb.g[2] = {cur1, wf[0], bf[0], nullptr, nullptr, k1};
            gb.g[3] = {cur2, wf[1], bf[1], nullptr, nullptr, k2};
            gb.g[4] = {cur1, wf[2], bf[2], nullptr, nullptr, v1};
            gb.g[5] = {cur2, wf[3], bf[3], nullptr, nullptr, v2};
            gemm_kernel<<<dim3(GEMM_GRID, 6), 256>>>(gb, N1, HID, 0, 0);
        }
        {
            AttnBatch ab;
            ab.a[0] = {q2, k1, v1, csr12, off12, prior + i0 * NHEAD, agg2};
            ab.a[1] = {q1, k2, v2, csr21, off21, prior + i1 * NHEAD, agg1};
            attn_kernel<<<dim3(ATTN_GRID, 2), 256>>>(ab, N1);
        }
        float* out1 = f1 + (size_t)l * N1 * HID;
        float* out2 = f2 + (size_t)l * N2 * HID;
        {
            GemmBatch gb = {};
            gb.g[0] = {agg1, Wa + (size_t)i0 * HID * HID, ba + (size_t)i0 * HID, cur1, skip + i0, out1};
            gb.g[1] = {agg2, Wa + (size_t)i1 * HID * HID, ba + (size_t)i1 * HID, cur2, skip + i1, out2};
            gemm_kernel<<<dim3(GEMM_GRID, 2), 256>>>(gb, N1, HID, 1, 2);
        }
        cur1 = out1;
        cur2 = out2;
    }

    pred_kernel<<<PRED_BLOCKS, 256>>>(f1, f1 + (size_t)N1 * HID,
                                      f2, f2 + (size_t)N2 * HID,
                                      epair, epair + P_PAIRS, out, P_PAIRS);
}

// round 4
// speedup vs baseline: 4.3145x; 1.2098x over previous
#include <cuda_runtime.h>
#include <cuda_bf16.h>
#include <math.h>

#define N1 10000
#define N2 10000
#define F_IN 256
#define E_EDGES 480000
#define P_PAIRS 200000
#define HID 128
#define NHEAD 8
#define DH 16

// ---------------- scratch (device globals) ----------------
__device__ float g_h1[N1 * HID];
__device__ float g_h2[N2 * HID];
__device__ float g_q1[N1 * HID];
__device__ float g_k1[N1 * HID];
__device__ float g_v1[N1 * HID];
__device__ float g_q2[N2 * HID];
__device__ float g_k2[N2 * HID];
__device__ float g_v2[N2 * HID];
__device__ float g_f1[2 * N1 * HID];
__device__ float g_f2[2 * N2 * HID];
__device__ float g_agg1[N1 * HID];
__device__ float g_agg2[N2 * HID];
__device__ float g_Wf[4][HID * HID];
__device__ float g_bf[4][HID];
__device__ int g_cnt[2][N1];
__device__ int g_off[2][N1 + 1];
__device__ int g_pos[2][N1];
__device__ int g_csr_src[2][E_EDGES];

// ---------------- arg structs for batched launches ----------------
struct GemmArgs { const float* A; const float* B; const float* bias;
                  const float* Hprev; const float* skipp; float* C; };
struct GemmBatch { GemmArgs g[6]; };
struct FoldArgs { const float* W; const float* b; const float* rel; float* Wf; float* bf; };
struct FoldBatch { FoldArgs f[4]; };
struct AttnArgs { const float* q; const float* k; const float* v;
                  const int* csr; const int* off; const float* prior; float* agg; };
struct AttnBatch { AttnArgs a[2]; };

__device__ __forceinline__ float gelu_tanh(float x) {
    const float c = 0.7978845608028654f;
    float t = tanhf(c * (x + 0.044715f * x * x * x));
    return 0.5f * x * (1.0f + t);
}

// packed f32x2 helpers
#define PACK_DUP(D, S) asm("mov.b64 %0, {%1, %1};" : "=l"(D) : "f"(S))
#define FFMA2(ACC, AP, BD) asm("fma.rn.f32x2 %0, %1, %2, %0;" : "+l"(ACC) : "l"(AP), "l"(BD))

__device__ __forceinline__ float lo_of(unsigned long long u) {
    return __int_as_float((int)(unsigned)(u & 0xFFFFFFFFull));
}
__device__ __forceinline__ float hi_of(unsigned long long u) {
    return __int_as_float((int)(unsigned)(u >> 32));
}

// ---------------- CSR build ----------------
__global__ void hist2_kernel(const int* __restrict__ dst0, int* __restrict__ cnt0,
                             const int* __restrict__ dst1, int* __restrict__ cnt1, int E) {
    int t = blockIdx.x * blockDim.x + threadIdx.x;
    if (t < E) atomicAdd(cnt0 + dst0[t], 1);
    else if (t < 2 * E) atomicAdd(cnt1 + dst1[t - E], 1);
}

__global__ void scan2_kernel(const int* __restrict__ cnt0, int* __restrict__ off0, int* __restrict__ pos0,
                             const int* __restrict__ cnt1, int* __restrict__ off1, int* __restrict__ pos1,
                             int n) {
    const int* cnt = blockIdx.x ? cnt1 : cnt0;
    int* off = blockIdx.x ? off1 : off0;
    int* pos = blockIdx.x ? pos1 : pos0;
    __shared__ int warpsum[32];
    __shared__ int base_s;
    int tid = threadIdx.x, lane = tid & 31, wid = tid >> 5;
    if (tid == 0) base_s = 0;
    __syncthreads();
    for (int c0 = 0; c0 < n; c0 += 1024) {
        int i = c0 + tid;
        int v = (i < n) ? cnt[i] : 0;
        int x = v;
#pragma unroll
        for (int o = 1; o < 32; o <<= 1) {
            int t = __shfl_up_sync(0xFFFFFFFFu, x, o);
            if (lane >= o) x += t;
        }
        if (lane == 31) warpsum[wid] = x;
        __syncthreads();
        if (wid == 0) {
            int s = warpsum[lane];
#pragma unroll
            for (int o = 1; o < 32; o <<= 1) {
                int t = __shfl_up_sync(0xFFFFFFFFu, s, o);
                if (lane >= o) s += t;
            }
            warpsum[lane] = s;
        }
        __syncthreads();
        int add = (wid > 0) ? warpsum[wid - 1] : 0;
        int incl = x + add + base_s;
        int excl = incl - v;
        if (i < n) {
            off[i] = excl;
            pos[i] = excl;
            if (i == n - 1) off[n] = incl;
        }
        __syncthreads();
        if (tid == 1023) base_s = incl;
        __syncthreads();
    }
}

__global__ void scatter2_kernel(const int* __restrict__ src0, const int* __restrict__ dst0,
                                int* __restrict__ pos0, int* __restrict__ csr0,
                                const int* __restrict__ src1, const int* __restrict__ dst1,
                                int* __restrict__ pos1, int* __restrict__ csr1, int E) {
    int t = blockIdx.x * blockDim.x + threadIdx.x;
    if (t < E) {
        int p = atomicAdd(pos0 + dst0[t], 1);
        csr0[p] = src0[t];
    } else if (t < 2 * E) {
        int e = t - E;
        int p = atomicAdd(pos1 + dst1[e], 1);
        csr1[p] = src1[e];
    }
}

// ---------------- fold arel/mrel into projection weights (batched x4) ----------------
__global__ void fold_kernel(FoldBatch fb) {
    FoldArgs fa = fb.f[blockIdx.y];
    int t = blockIdx.x * blockDim.x + threadIdx.x;
    if (t >= HID * HID) return;
    int row = t >> 7;
    int col = t & 127;
    int h = col >> 4;
    int eo = col & 15;
    const float* relh = fa.rel + h * (DH * DH);
    const float* wrow = fa.W + row * HID + h * DH;
    float acc = 0.f;
#pragma unroll
    for (int d = 0; d < DH; d++) acc = fmaf(wrow[d], relh[d * DH + eo], acc);
    fa.Wf[t] = acc;
    if (row == 0) {
        const float* brow = fa.b + h * DH;
        float accb = 0.f;
#pragma unroll
        for (int d = 0; d < DH; d++) accb = fmaf(brow[d], relh[d * DH + eo], accb);
        fa.bf[col] = accb;
    }
}

// ---------------- GEMM: 128x128 tile, 8x8/thread, f32x2 FMA, double-buffered ----------------
// C[M,128] = epi( actA(A[M,K]) @ B[K,128] + bias )
__global__ void __launch_bounds__(256, 2) gemm_kernel(
    GemmBatch batch, int M, int K, int geluA, int epi) {
    GemmArgs ga = batch.g[blockIdx.y];
    const float* __restrict__ A = ga.A;
    const float* __restrict__ B = ga.B;

    __shared__ float As[2][16][132];   // [k][m], 16B-aligned rows, A-reads are broadcasts
    __shared__ float Bs[2][16][128];

    const int tid = threadIdx.x;
    const int m0 = blockIdx.x * 128;
    const int tr = tid >> 4;           // 0..15 -> rows tr*8 .. +7
    const int tc = tid & 15;           // 0..15 -> cols tc*8 .. +7

    // loader mapping
    const int la_r = tid >> 1;          // 0..127
    const int la_k = (tid & 1) << 3;    // 0 or 8
    const int lb_k = tid >> 4;          // 0..15
    const int lb_n = (tid & 15) << 3;   // 0..120

    const int grow = m0 + la_r;
    const bool arow_ok = (grow < M);
    const float* aptr = A + (size_t)grow * K + la_k;
    const float* bptr = B + (size_t)lb_k * HID + lb_n;

    unsigned long long acc[4][8];
#pragma unroll
    for (int i = 0; i < 4; i++)
#pragma unroll
        for (int j = 0; j < 8; j++) acc[i][j] = 0ull;

    const int nc = K >> 4;

    float4 a0, a1, b0, b1;
    // prologue: load chunk 0
    if (arow_ok) {
        a0 = *(const float4*)(aptr);
        a1 = *(const float4*)(aptr + 4);
    } else {
        a0 = make_float4(0.f, 0.f, 0.f, 0.f);
        a1 = a0;
    }
    b0 = *(const float4*)(bptr);
    b1 = *(const float4*)(bptr + 4);

    for (int c = 0; c < nc; c++) {
        int cur = c & 1;
        // stage current regs -> smem
        if (geluA) {
            a0.x = gelu_tanh(a0.x); a0.y = gelu_tanh(a0.y);
            a0.z = gelu_tanh(a0.z); a0.w = gelu_tanh(a0.w);
            a1.x = gelu_tanh(a1.x); a1.y = gelu_tanh(a1.y);
            a1.z = gelu_tanh(a1.z); a1.w = gelu_tanh(a1.w);
        }
        As[cur][la_k + 0][la_r] = a0.x;
        As[cur][la_k + 1][la_r] = a0.y;
        As[cur][la_k + 2][la_r] = a0.z;
        As[cur][la_k + 3][la_r] = a0.w;
        As[cur][la_k + 4][la_r] = a1.x;
        As[cur][la_k + 5][la_r] = a1.y;
        As[cur][la_k + 6][la_r] = a1.z;
        As[cur][la_k + 7][la_r] = a1.w;
        *(float4*)&Bs[cur][lb_k][lb_n] = b0;
        *(float4*)&Bs[cur][lb_k][lb_n + 4] = b1;
        __syncthreads();

        // prefetch next chunk while computing
        if (c + 1 < nc) {
            const float* ap = aptr + (c + 1) * 16;
            const float* bp = bptr + (size_t)(c + 1) * 16 * HID;
            if (arow_ok) {
                a0 = *(const float4*)(ap);
                a1 = *(const float4*)(ap + 4);
            } else {
                a0 = make_float4(0.f, 0.f, 0.f, 0.f);
                a1 = a0;
            }
            b0 = *(const float4*)(bp);
            b1 = *(const float4*)(bp + 4);
        }

#pragma unroll
        for (int kk = 0; kk < 16; kk++) {
            ulonglong2 apq0 = *(const ulonglong2*)&As[cur][kk][tr << 3];
            ulonglong2 apq1 = *(const ulonglong2*)&As[cur][kk][(tr << 3) + 4];
            float4 bv0 = *(const float4*)&Bs[cur][kk][tc << 3];
            float4 bv1 = *(const float4*)&Bs[cur][kk][(tc << 3) + 4];
            unsigned long long ap0 = apq0.x, ap1 = apq0.y, ap2 = apq1.x, ap3 = apq1.y;
            unsigned long long bd;
#define COL(J, BV) \
            PACK_DUP(bd, BV); \
            FFMA2(acc[0][J], ap0, bd); FFMA2(acc[1][J], ap1, bd); \
            FFMA2(acc[2][J], ap2, bd); FFMA2(acc[3][J], ap3, bd);
            COL(0, bv0.x) COL(1, bv0.y) COL(2, bv0.z) COL(3, bv0.w)
            COL(4, bv1.x) COL(5, bv1.y) COL(6, bv1.z) COL(7, bv1.w)
#undef COL
        }
        __syncthreads();
    }

    // epilogue
    float4 bias0 = *(const float4*)(ga.bias + (tc << 3));
    float4 bias1 = *(const float4*)(ga.bias + (tc << 3) + 4);
    float bb[8] = {bias0.x, bias0.y, bias0.z, bias0.w, bias1.x, bias1.y, bias1.z, bias1.w};
    float sg = 0.f;
    if (epi == 2) sg = 1.f / (1.f + __expf(-ga.skipp[0]));

#pragma unroll
    for (int p = 0; p < 4; p++) {
#pragma unroll
        for (int half = 0; half < 2; half++) {
            int gm = m0 + (tr << 3) + (p << 1) + half;
            if (gm >= M) continue;
            float o[8];
#pragma unroll
            for (int j = 0; j < 8; j++) {
                unsigned long long u = acc[p][j];
                float v = half ? hi_of(u) : lo_of(u);
                v += bb[j];
                if (epi == 1) v = fmaxf(v, 0.f);
                o[j] = v;
            }
            float* cp = ga.C + (size_t)gm * HID + (tc << 3);
            if (epi == 2) {
                const float* hp = ga.Hprev + (size_t)gm * HID + (tc << 3);
                float4 h0 = *(const float4*)(hp);
                float4 h1 = *(const float4*)(hp + 4);
                o[0] = sg * o[0] + (1.f - sg) * h0.x;
                o[1] = sg * o[1] + (1.f - sg) * h0.y;
                o[2] = sg * o[2] + (1.f - sg) * h0.z;
                o[3] = sg * o[3] + (1.f - sg) * h0.w;
                o[4] = sg * o[4] + (1.f - sg) * h1.x;
                o[5] = sg * o[5] + (1.f - sg) * h1.y;
                o[6] = sg * o[6] + (1.f - sg) * h1.z;
                o[7] = sg * o[7] + (1.f - sg) * h1.w;
            }
            *(float4*)(cp) = make_float4(o[0], o[1], o[2], o[3]);
            *(float4*)(cp + 4) = make_float4(o[4], o[5], o[6], o[7]);
        }
    }
}

// ---------------- attention: warp/dst node, online softmax, 2-edge unroll, batched x2 ----------------
__global__ void __launch_bounds__(256) attn_kernel(AttnBatch ab, int n) {
    AttnArgs aa = ab.a[blockIdx.y];
    int node = blockIdx.x * 8 + (threadIdx.x >> 5);
    if (node >= n) return;
    int lane = threadIdx.x & 31;
    int h = lane >> 2;

    int beg = aa.off[node];
    int end = aa.off[node + 1];
    float4 qv = ((const float4*)(aa.q + (size_t)node * HID))[lane];
    float pr = aa.prior[h] * 0.25f;  // 1/sqrt(16)

    float m = -INFINITY, s = 0.f;
    float ax = 0.f, ay = 0.f, az = 0.f, aw = 0.f;

    int i = beg;
    for (; i + 1 < end; i += 2) {
        int sn0 = aa.csr[i];
        int sn1 = aa.csr[i + 1];
        float4 k0 = ((const float4*)(aa.k + (size_t)sn0 * HID))[lane];
        float4 v0 = ((const float4*)(aa.v + (size_t)sn0 * HID))[lane];
        float4 k1 = ((const float4*)(aa.k + (size_t)sn1 * HID))[lane];
        float4 v1 = ((const float4*)(aa.v + (size_t)sn1 * HID))[lane];
        float d0 = qv.x * k0.x + qv.y * k0.y + qv.z * k0.z + qv.w * k0.w;
        float d1 = qv.x * k1.x + qv.y * k1.y + qv.z * k1.z + qv.w * k1.w;
        d0 += __shfl_xor_sync(0xFFFFFFFFu, d0, 1);
        d1 += __shfl_xor_sync(0xFFFFFFFFu, d1, 1);
        d0 += __shfl_xor_sync(0xFFFFFFFFu, d0, 2);
        d1 += __shfl_xor_sync(0xFFFFFFFFu, d1, 2);
        float lg0 = d0 * pr, lg1 = d1 * pr;
        float nm = fmaxf(m, fmaxf(lg0, lg1));
        float c = __expf(m - nm);
        float w0 = __expf(lg0 - nm);
        float w1 = __expf(lg1 - nm);
        m = nm;
        s = s * c + w0 + w1;
        ax = ax * c + w0 * v0.x + w1 * v1.x;
        ay = ay * c + w0 * v0.y + w1 * v1.y;
        az = az * c + w0 * v0.z + w1 * v1.z;
        aw = aw * c + w0 * v0.w + w1 * v1.w;
    }
    if (i < end) {
        int sn = aa.csr[i];
        float4 kv = ((const float4*)(aa.k + (size_t)sn * HID))[lane];
        float4 vv = ((const float4*)(aa.v + (size_t)sn * HID))[lane];
        float d = qv.x * kv.x + qv.y * kv.y + qv.z * kv.z + qv.w * kv.w;
        d += __shfl_xor_sync(0xFFFFFFFFu, d, 1);
        d += __shfl_xor_sync(0xFFFFFFFFu, d, 2);
        float lg = d * pr;
        float nm = fmaxf(m, lg);
        float c = __expf(m - nm);
        float w = __expf(lg - nm);
        m = nm;
        s = s * c + w;
        ax = ax * c + w * vv.x;
        ay = ay * c + w * vv.y;
        az = az * c + w * vv.z;
        aw = aw * c + w * vv.w;
    }
    float inv = 1.f / (s + 1e-16f);
    ((float4*)(aa.agg + (size_t)node * HID))[lane] = make_float4(ax * inv, ay * inv, az * inv, aw * inv);
}

// ---------------- pair scoring ----------------
__global__ void pred_kernel(const float* __restrict__ f1a, const float* __restrict__ f1b,
                            const float* __restrict__ f2a, const float* __restrict__ f2b,
                            const int* __restrict__ mi, const int* __restrict__ di,
                            float* __restrict__ out, int P) {
    int gw = (blockIdx.x * blockDim.x + threadIdx.x) >> 5;
    int lane = threadIdx.x & 31;
    if (gw >= P) return;
    int mm = mi[gw];
    int dd = di[gw];
    float4 a0 = ((const float4*)(f1a + (size_t)mm * HID))[lane];
    float4 b0 = ((const float4*)(f2a + (size_t)dd * HID))[lane];
    float4 a1 = ((const float4*)(f1b + (size_t)mm * HID))[lane];
    float4 b1 = ((const float4*)(f2b + (size_t)dd * HID))[lane];
    float acc = a0.x * b0.x + a0.y * b0.y + a0.z * b0.z + a0.w * b0.w
              + a1.x * b1.x + a1.y * b1.y + a1.z * b1.z + a1.w * b1.w;
#pragma unroll
    for (int o = 16; o > 0; o >>= 1) acc += __shfl_xor_sync(0xFFFFFFFFu, acc, o);
    if (lane == 0) out[gw] = acc;
}

// ---------------- host orchestration ----------------
extern "C" void kernel_launch(void* const* d_in, const int* in_sizes, int n_in,
                              void* d_out, int out_size) {
    const float* x1    = (const float*)d_in[0];
    const float* x2    = (const float*)d_in[1];
    const int*   ei12  = (const int*)d_in[2];
    const int*   ei21  = (const int*)d_in[3];
    const int*   epair = (const int*)d_in[4];
    const float* Win1  = (const float*)d_in[5];
    const float* bin1  = (const float*)d_in[6];
    const float* Win2  = (const float*)d_in[7];
    const float* bin2  = (const float*)d_in[8];
    const float* Wk    = (const float*)d_in[9];
    const float* bk    = (const float*)d_in[10];
    const float* Wq    = (const float*)d_in[11];
    const float* bq    = (const float*)d_in[12];
    const float* Wv    = (const float*)d_in[13];
    const float* bv    = (const float*)d_in[14];
    const float* Wa    = (const float*)d_in[15];
    const float* ba    = (const float*)d_in[16];
    const float* skip  = (const float*)d_in[17];
    const float* arel  = (const float*)d_in[18];
    const float* mrel  = (const float*)d_in[19];
    const float* prior = (const float*)d_in[20];
    float* out = (float*)d_out;

    void* p;
#define SYMF(var, sym) cudaGetSymbolAddress(&p, sym); float* var = (float*)p;
#define SYMI(var, sym) cudaGetSymbolAddress(&p, sym); int* var = (int*)p;
    SYMF(h1, g_h1) SYMF(h2, g_h2)
    SYMF(q1, g_q1) SYMF(k1, g_k1) SYMF(v1, g_v1)
    SYMF(q2, g_q2) SYMF(k2, g_k2) SYMF(v2, g_v2)
    SYMF(f1, g_f1) SYMF(f2, g_f2)
    SYMF(agg1, g_agg1) SYMF(agg2, g_agg2)
    SYMF(wfbase, g_Wf) SYMF(bfbase, g_bf)
    SYMI(cnt, g_cnt) SYMI(off, g_off) SYMI(pos, g_pos) SYMI(csr, g_csr_src)
#undef SYMF
#undef SYMI
    float* wf[4]; float* bf[4];
    for (int i = 0; i < 4; i++) { wf[i] = wfbase + i * HID * HID; bf[i] = bfbase + i * HID; }
    int* cnt12 = cnt;  int* cnt21 = cnt + N1;
    int* off12 = off;  int* off21 = off + (N1 + 1);
    int* pos12 = pos;  int* pos21 = pos + N1;
    int* csr12 = csr;  int* csr21 = csr + E_EDGES;

    const int GEMM_GRID = (N1 + 127) / 128;   // 79
    const int E2_BLOCKS = (2 * E_EDGES + 255) / 256;
    const int ATTN_GRID = (N1 + 7) / 8;
    const int PRED_BLOCKS = (P_PAIRS * 32 + 255) / 256;

    // ---- CSR build (both graphs per launch) ----
    cudaMemsetAsync(cnt12, 0, (size_t)2 * N1 * 4);
    hist2_kernel<<<E2_BLOCKS, 256>>>(ei12 + E_EDGES, cnt12, ei21 + E_EDGES, cnt21, E_EDGES);
    scan2_kernel<<<2, 1024>>>(cnt12, off12, pos12, cnt21, off21, pos21, N1);
    scatter2_kernel<<<E2_BLOCKS, 256>>>(ei12, ei12 + E_EDGES, pos12, csr12,
                                        ei21, ei21 + E_EDGES, pos21, csr21, E_EDGES);

    // ---- input projections + relu (batched x2) ----
    {
        GemmBatch gb = {};
        gb.g[0] = {x1, Win1, bin1, nullptr, nullptr, h1};
        gb.g[1] = {x2, Win2, bin2, nullptr, nullptr, h2};
        gemm_kernel<<<dim3(GEMM_GRID, 2), 256>>>(gb, N1, F_IN, 0, 1);
    }

    const float* cur1 = h1;
    const float* cur2 = h2;

    for (int l = 0; l < 2; l++) {
        const int i0 = l * 2 + 0, i1 = l * 2 + 1;
        {
            FoldBatch fb;
            fb.f[0] = {Wk + (size_t)i0 * HID * HID, bk + (size_t)i0 * HID,
                       arel + (size_t)i0 * NHEAD * DH * DH, wf[0], bf[0]};
            fb.f[1] = {Wk + (size_t)i1 * HID * HID, bk + (size_t)i1 * HID,
                       arel + (size_t)i1 * NHEAD * DH * DH, wf[1], bf[1]};
            fb.f[2] = {Wv + (size_t)i0 * HID * HID, bv + (size_t)i0 * HID,
                       mrel + (size_t)i0 * NHEAD * DH * DH, wf[2], bf[2]};
            fb.f[3] = {Wv + (size_t)i1 * HID * HID, bv + (size_t)i1 * HID,
                       mrel + (size_t)i1 * NHEAD * DH * DH, wf[3], bf[3]};
            fold_kernel<<<dim3(64, 4), 256>>>(fb);
        }
        {
            GemmBatch gb;
            gb.g[0] = {cur1, Wq + (size_t)i0 * HID * HID, bq + (size_t)i0 * HID, nullptr, nullptr, q1};
            gb.g[1] = {cur2, Wq + (size_t)i1 * HID * HID, bq + (size_t)i1 * HID, nullptr, nullptr, q2};
            gb.g[2] = {cur1, wf[0], bf[0], nullptr, nullptr, k1};
            gb.g[3] = {cur2, wf[1], bf[1], nullptr, nullptr, k2};
            gb.g[4] = {cur1, wf[2], bf[2], nullptr, nullptr, v1};
            gb.g[5] = {cur2, wf[3], bf[3], nullptr, nullptr, v2};
            gemm_kernel<<<dim3(GEMM_GRID, 6), 256>>>(gb, N1, HID, 0, 0);
        }
        {
            AttnBatch ab;
            ab.a[0] = {q2, k1, v1, csr12, off12, prior + i0 * NHEAD, agg2};
            ab.a[1] = {q1, k2, v2, csr21, off21, prior + i1 * NHEAD, agg1};
            attn_kernel<<<dim3(ATTN_GRID, 2), 256>>>(ab, N1);
        }
        float* out1 = f1 + (size_t)l * N1 * HID;
        float* out2 = f2 + (size_t)l * N2 * HID;
        {
            GemmBatch gb = {};
            gb.g[0] = {agg1, Wa + (size_t)i0 * HID * HID, ba + (size_t)i0 * HID, cur1, skip + i0, out1};
            gb.g[1] = {agg2, Wa + (size_t)i1 * HID * HID, ba + (size_t)i1 * HID, cur2, skip + i1, out2};
            gemm_kernel<<<dim3(GEMM_GRID, 2), 256>>>(gb, N1, HID, 1, 2);
        }
        cur1 = out1;
        cur2 = out2;
    }

    pred_kernel<<<PRED_BLOCKS, 256>>>(f1, f1 + (size_t)N1 * HID,
                                      f2, f2 + (size_t)N2 * HID,
                                      epair, epair + P_PAIRS, out, P_PAIRS);
}